// round 14
// baseline (speedup 1.0000x reference)
#include <cuda_runtime.h>
#include <cuda_fp16.h>
#include <cstdint>

#define NT 512
#define ROWS 128

struct Smem {
    __half W[3][16384];      // phase weights (swizzled, prescaled)
    __half h0[2][8192];      // [buf][row*64 + unit], 128B rows, 16B-chunk swizzle
    __half h1[2][8192];
    float wx[512], b0[256], b1[256];
    float fcw[128], fcb[2];
    float fcpart[8][ROWS][2];
    float pred[ROWS * 2];
    float obs[ROWS * 16];
};

__device__ __forceinline__ float tanhg(float x) {
    float r; asm("tanh.approx.f32 %0, %1;" : "=f"(r) : "f"(x)); return r;
}
__device__ __forceinline__ uint32_t smem_u32(const void* p) {
    uint32_t a;
    asm("{ .reg .u64 t; cvta.to.shared.u64 t, %1; cvt.u32.u64 %0, t; }"
        : "=r"(a) : "l"(p));
    return a;
}
__device__ __forceinline__ void ldm4(uint32_t* f, uint32_t addr) {
    asm volatile("ldmatrix.sync.aligned.m8n8.x4.shared.b16 {%0,%1,%2,%3}, [%4];"
        : "=r"(f[0]), "=r"(f[1]), "=r"(f[2]), "=r"(f[3]) : "r"(addr));
}
__device__ __forceinline__ void mma16(float* d, uint32_t a0, uint32_t a1,
                                      uint32_t a2, uint32_t a3,
                                      uint32_t b0, uint32_t b1) {
    asm volatile(
        "mma.sync.aligned.m16n8k16.row.col.f32.f16.f16.f32 "
        "{%0,%1,%2,%3},{%4,%5,%6,%7},{%8,%9},{%0,%1,%2,%3};"
        : "+f"(d[0]), "+f"(d[1]), "+f"(d[2]), "+f"(d[3])
        : "r"(a0), "r"(a1), "r"(a2), "r"(a3), "r"(b0), "r"(b1));
}

// W[g][k] fp32 global -> fp16 smem, prescaled (0.5 i/f/o, 1.0 g gate);
// 16B chunk c of row g stored at chunk c ^ (g&7).
__device__ __forceinline__ void loadW(__half* Wt, const float* __restrict__ G) {
    for (int i = threadIdx.x; i < 8192; i += NT) {
        int g = i >> 5, w = i & 31;
        float sc = ((g >> 6) == 2) ? 1.0f : 0.5f;
        float2 v = *(const float2*)(G + g * 64 + 2 * w);
        int pos = (w >> 2) ^ (g & 7);
        *(__half2*)(Wt + g * 64 + pos * 8 + (w & 3) * 2) =
            __floats2half2_rn(v.x * sc, v.y * sc);
    }
}
__device__ __forceinline__ void loadSmall(float* wx, float* b0, float* b1,
                                          const float* Wih0,
                                          const float* Bi0, const float* Bh0,
                                          const float* Bi1, const float* Bh1) {
    for (int g = threadIdx.x; g < 256; g += NT) {
        float sc = ((g >> 6) == 2) ? 1.0f : 0.5f;
        wx[2 * g] = Wih0[2 * g] * sc;
        wx[2 * g + 1] = Wih0[2 * g + 1] * sc;
        b0[g] = (Bi0[g] + Bh0[g]) * sc;
        b1[g] = (Bi1[g] + Bh1[g]) * sc;
    }
}
// Load this warp's weight-fragment slice (units uw*8..+8 of each gate).
__device__ __forceinline__ void loadFrags(uint32_t (*f)[8], uint32_t mbase,
                                          int uw, uint32_t lmoff) {
#pragma unroll
    for (int gt = 0; gt < 4; gt++) {
        uint32_t a0 = mbase + (uint32_t)((gt * 64 + uw * 8) * 128) + lmoff;
        ldm4(f[gt], a0);
        ldm4(f[gt] + 4, a0 ^ 64u);
    }
}
// Load one st-tile of A fragments (16 rows x 64 k).
__device__ __forceinline__ void ldA(uint32_t* f, uint32_t hA, int st,
                                    int arow, int acb, int j) {
#pragma unroll
    for (int kc = 0; kc < 4; kc++)
        ldm4(f + 4 * kc,
             hA + st * 2048 + arow * 128 + ((((kc << 1) | acb) ^ j) << 4));
}

// One layer step for this warp: units uw*8..+8, rows rh*64..+64 (4 st tiles).
// gates = hA0 @ Wa^T (+ hA1 @ Wb^T if L1MODE) (+ x@wx if HASX).
// Weight frags reloaded per GEMM to cap register pressure (16 warps).
template <bool L1MODE, bool HASX, bool FC>
__device__ __forceinline__ void stepLayer(
    uint32_t hA0, uint32_t hA1, __half* hout,
    uint32_t wWa, uint32_t wWb,
    const float* bias, const float* wx, const float* xb, int xstr,
    const float* fcw, float* fcpart, float* c,
    int uw, int rh, int l4, int lm4, int arow, int acb, int j, uint32_t lmoff)
{
#pragma unroll
    for (int st4 = 0; st4 < 4; st4++) {
        const int st = rh * 4 + st4;
        float d[4][4];
#pragma unroll
        for (int gt = 0; gt < 4; gt++) {
            float2 bb = *(const float2*)(bias + gt * 64 + uw * 8 + 2 * lm4);
            d[gt][0] = bb.x; d[gt][1] = bb.y; d[gt][2] = bb.x; d[gt][3] = bb.y;
        }
        {   // GEMM A: hA0 @ Wa
            uint32_t fW[4][8];
            loadFrags(fW, wWa, uw, lmoff);
            uint32_t fa[16];
            ldA(fa, hA0, st, arow, acb, j);
#pragma unroll
            for (int kc = 0; kc < 4; kc++)
#pragma unroll
                for (int gt = 0; gt < 4; gt++)
                    mma16(d[gt], fa[4 * kc], fa[4 * kc + 1], fa[4 * kc + 2],
                          fa[4 * kc + 3], fW[gt][2 * kc], fW[gt][2 * kc + 1]);
        }
        if (L1MODE) {   // GEMM B: hA1 @ Wb (reuses fragment registers)
            uint32_t fW[4][8];
            loadFrags(fW, wWb, uw, lmoff);
            uint32_t fa[16];
            ldA(fa, hA1, st, arow, acb, j);
#pragma unroll
            for (int kc = 0; kc < 4; kc++)
#pragma unroll
                for (int gt = 0; gt < 4; gt++)
                    mma16(d[gt], fa[4 * kc], fa[4 * kc + 1], fa[4 * kc + 2],
                          fa[4 * kc + 3], fW[gt][2 * kc], fW[gt][2 * kc + 1]);
        }
        float x0l, x1l, x0h, x1h;
        float4 wi, wf, wg, wo;
        if (HASX) {
            float2 va = *(const float2*)(xb + (st * 16 + l4) * xstr);
            float2 vb = *(const float2*)(xb + (st * 16 + l4 + 8) * xstr);
            x0l = va.x; x1l = va.y; x0h = vb.x; x1h = vb.y;
            wi = *(const float4*)(wx + uw * 16 + 4 * lm4);
            wf = *(const float4*)(wx + 128 + uw * 16 + 4 * lm4);
            wg = *(const float4*)(wx + 256 + uw * 16 + 4 * lm4);
            wo = *(const float4*)(wx + 384 + uw * 16 + 4 * lm4);
        }
        float hv[4];
#pragma unroll
        for (int e = 0; e < 4; e++) {
            const int o = e & 1;
            float gi = d[0][e], gf = d[1][e], gg = d[2][e], go = d[3][e];
            if (HASX) {
                float xa = (e < 2) ? x0l : x0h, xv = (e < 2) ? x1l : x1h;
                gi += xa * (o ? wi.z : wi.x) + xv * (o ? wi.w : wi.y);
                gf += xa * (o ? wf.z : wf.x) + xv * (o ? wf.w : wf.y);
                gg += xa * (o ? wg.z : wg.x) + xv * (o ? wg.w : wg.y);
                go += xa * (o ? wo.z : wo.x) + xv * (o ? wo.w : wo.y);
            }
            float ti = tanhg(gi), tf_ = tanhg(gf), tg = tanhg(gg), to = tanhg(go);
            float si = fmaf(0.5f, ti, 0.5f);
            float sf = fmaf(0.5f, tf_, 0.5f);
            float so = fmaf(0.5f, to, 0.5f);
            float cc = c[st4 * 4 + e];
            cc = fmaf(si, tg, sf * cc);
            c[st4 * 4 + e] = cc;
            hv[e] = so * tanhg(cc);
        }
        if (FC) {
            float2 f0v = *(const float2*)(fcw + uw * 8 + 2 * lm4);
            float2 f1v = *(const float2*)(fcw + 64 + uw * 8 + 2 * lm4);
            float sfc[4];
            sfc[0] = hv[0] * f0v.x + hv[1] * f0v.y;
            sfc[1] = hv[0] * f1v.x + hv[1] * f1v.y;
            sfc[2] = hv[2] * f0v.x + hv[3] * f0v.y;
            sfc[3] = hv[2] * f1v.x + hv[3] * f1v.y;
#pragma unroll
            for (int i = 0; i < 4; i++) {
                sfc[i] += __shfl_xor_sync(0xffffffffu, sfc[i], 1);
                sfc[i] += __shfl_xor_sync(0xffffffffu, sfc[i], 2);
            }
            if (lm4 == 0) {
                *(float2*)(fcpart + (st * 16 + l4) * 2) = make_float2(sfc[0], sfc[1]);
                *(float2*)(fcpart + (st * 16 + l4 + 8) * 2) = make_float2(sfc[2], sfc[3]);
            }
        }
        {
            __half2 plo = __floats2half2_rn(hv[0], hv[1]);
            __half2 phi = __floats2half2_rn(hv[2], hv[3]);
            int r0 = st * 16 + l4;
            int co = ((uw ^ l4) << 4) + lm4 * 4;
            *(__half2*)((char*)hout + r0 * 128 + co) = plo;
            *(__half2*)((char*)hout + (r0 + 8) * 128 + co) = phi;
        }
    }
}

__global__ __launch_bounds__(NT, 1)
void SimpleLSTM_49709951484004_kernel(
    const float* __restrict__ obs,
    const float* __restrict__ eWih0, const float* __restrict__ eWhh0,
    const float* __restrict__ eBih0, const float* __restrict__ eBhh0,
    const float* __restrict__ eWih1, const float* __restrict__ eWhh1,
    const float* __restrict__ eBih1, const float* __restrict__ eBhh1,
    const float* __restrict__ dWih0, const float* __restrict__ dWhh0,
    const float* __restrict__ dBih0, const float* __restrict__ dBhh0,
    const float* __restrict__ dWih1, const float* __restrict__ dWhh1,
    const float* __restrict__ dBih1, const float* __restrict__ dBhh1,
    const float* __restrict__ fcW, const float* __restrict__ fcb,
    float* __restrict__ out, int Btot)
{
    extern __shared__ char smraw[];
    Smem* s = (Smem*)smraw;
    const int tid = threadIdx.x;
    const int w = tid >> 5, l = tid & 31, l4 = l >> 2, lm4 = l & 3;
    const int uw = w & 7, rh = w >> 3;
    const int j = l & 7, tt = l >> 3;
    const uint32_t lmoff = (uint32_t)(j * 128 + (((tt ^ j) & 7) << 4)); // B-pattern
    const int arow = (l & 7) + ((l >> 3) & 1) * 8;                      // A-pattern
    const int acb = (l >> 4) & 1;
    const long base = (long)blockIdx.x * ROWS;

    for (int i = tid; i < ROWS * 16; i += NT)
        s->obs[i] = (base + i / 16 < Btot) ? obs[base * 16 + i] : 0.f;
    loadW(s->W[0], eWhh0); loadW(s->W[1], eWih1); loadW(s->W[2], eWhh1);
    loadSmall(s->wx, s->b0, s->b1, eWih0, eBih0, eBhh0, eBih1, eBhh1);
    if (tid < 128) s->fcw[tid] = fcW[tid];
    if (tid < 2) s->fcb[tid] = fcb[tid];
    for (int i = tid; i < 4096; i += NT) {
        ((uint32_t*)s->h0[0])[i] = 0u;
        ((uint32_t*)s->h1[0])[i] = 0u;
    }
    __syncthreads();

    const uint32_t uW = smem_u32(s->W[0]);
    const uint32_t uh0[2] = { smem_u32(s->h0[0]), smem_u32(s->h0[1]) };
    const uint32_t uh1[2] = { smem_u32(s->h1[0]), smem_u32(s->h1[1]) };

    float c0[16], c1[16];
#pragma unroll
    for (int i = 0; i < 16; i++) { c0[i] = 0.f; c1[i] = 0.f; }
    int p0 = 0, p1 = 0;

    // ---------------- encoder: 8 steps ----------------
#pragma unroll 1
    for (int t = 0; t < 8; t++) {
        stepLayer<false, true, false>(uh0[p0], 0u, s->h0[p0 ^ 1], uW, 0u,
                                      s->b0, s->wx, s->obs + 2 * t, 16,
                                      nullptr, nullptr, c0,
                                      uw, rh, l4, lm4, arow, acb, j, lmoff);
        __syncthreads();
        // Wa (x hA0=h0_new) = Wih1 = W[1]; Wb (x hA1=h1_old) = Whh1 = W[2]
        stepLayer<true, false, false>(uh0[p0 ^ 1], uh1[p1], s->h1[p1 ^ 1],
                                      uW + 32768u, uW + 65536u,
                                      s->b1, nullptr, nullptr, 0,
                                      nullptr, nullptr, c1,
                                      uw, rh, l4, lm4, arow, acb, j, lmoff);
        __syncthreads();
        p0 ^= 1; p1 ^= 1;
    }

    // ---------------- phase switch ----------------
    loadW(s->W[0], dWhh0); loadW(s->W[1], dWih1); loadW(s->W[2], dWhh1);
    loadSmall(s->wx, s->b0, s->b1, dWih0, dBih0, dBhh0, dBih1, dBhh1);
    __syncthreads();

    // ---------------- decoder: 12 steps ----------------
#pragma unroll 1
    for (int t = 0; t < 12; t++) {
        const float* xb = (t == 0) ? (s->obs + 14) : s->pred;
        const int xstr = (t == 0) ? 16 : 2;
        stepLayer<false, true, false>(uh0[p0], 0u, s->h0[p0 ^ 1], uW, 0u,
                                      s->b0, s->wx, xb, xstr,
                                      nullptr, nullptr, c0,
                                      uw, rh, l4, lm4, arow, acb, j, lmoff);
        __syncthreads();
        stepLayer<true, false, true>(uh0[p0 ^ 1], uh1[p1], s->h1[p1 ^ 1],
                                     uW + 32768u, uW + 65536u,
                                     s->b1, nullptr, nullptr, 0,
                                     s->fcw, &s->fcpart[uw][0][0], c1,
                                     uw, rh, l4, lm4, arow, acb, j, lmoff);
        __syncthreads();
        {
            int rr = tid & 127, o = (tid >> 7) & 1;
            float v = s->fcb[o];
#pragma unroll
            for (int w8 = 0; w8 < 8; w8++) v += s->fcpart[w8][rr][o];
            s->pred[rr * 2 + o] = v;
            long gr = base + rr;
            if (gr < Btot && tid < 256) out[gr * 24 + t * 2 + o] = v;
        }
        __syncthreads();
        p0 ^= 1; p1 ^= 1;
    }
}

extern "C" void kernel_launch(void* const* d_in, const int* in_sizes, int n_in,
                              void* d_out, int out_size) {
    int Btot = in_sizes[0] / 16;
    int grid = (Btot + ROWS - 1) / ROWS;
    cudaFuncSetAttribute(SimpleLSTM_49709951484004_kernel,
                         cudaFuncAttributeMaxDynamicSharedMemorySize,
                         (int)sizeof(Smem));
    SimpleLSTM_49709951484004_kernel<<<grid, NT, sizeof(Smem)>>>(
        (const float*)d_in[0], (const float*)d_in[1], (const float*)d_in[2],
        (const float*)d_in[3], (const float*)d_in[4], (const float*)d_in[5],
        (const float*)d_in[6], (const float*)d_in[7], (const float*)d_in[8],
        (const float*)d_in[9], (const float*)d_in[10], (const float*)d_in[11],
        (const float*)d_in[12], (const float*)d_in[13], (const float*)d_in[14],
        (const float*)d_in[15], (const float*)d_in[16], (const float*)d_in[17],
        (const float*)d_in[18], (float*)d_out, Btot);
}

// round 15
// speedup vs baseline: 1.2079x; 1.2079x over previous
#include <cuda_runtime.h>
#include <cuda_fp16.h>
#include <cstdint>

#define NT 256
#define ROWS 128

struct Smem {
    __half W[3][16384];      // phase weights (swizzled, prescaled)
    __half h0[2][8192];      // [buf][row*64 + unit], 128B rows, 16B-chunk swizzle
    __half h1[2][8192];
    float wx[512], b0[256], b1[256];
    float fcw[128], fcb[2];
    float fcpart[8][ROWS][2];
    float pred[ROWS * 2];
    float obs[ROWS * 16];
};

__device__ __forceinline__ float tanhg(float x) {
    float r; asm("tanh.approx.f32 %0, %1;" : "=f"(r) : "f"(x)); return r;
}
__device__ __forceinline__ uint32_t smem_u32(const void* p) {
    uint32_t a;
    asm("{ .reg .u64 t; cvta.to.shared.u64 t, %1; cvt.u32.u64 %0, t; }"
        : "=r"(a) : "l"(p));
    return a;
}
__device__ __forceinline__ void ldm4(uint32_t* f, uint32_t addr) {
    asm volatile("ldmatrix.sync.aligned.m8n8.x4.shared.b16 {%0,%1,%2,%3}, [%4];"
        : "=r"(f[0]), "=r"(f[1]), "=r"(f[2]), "=r"(f[3]) : "r"(addr));
}
__device__ __forceinline__ void mma16(float* d, uint32_t a0, uint32_t a1,
                                      uint32_t a2, uint32_t a3,
                                      uint32_t b0, uint32_t b1) {
    asm volatile(
        "mma.sync.aligned.m16n8k16.row.col.f32.f16.f16.f32 "
        "{%0,%1,%2,%3},{%4,%5,%6,%7},{%8,%9},{%0,%1,%2,%3};"
        : "+f"(d[0]), "+f"(d[1]), "+f"(d[2]), "+f"(d[3])
        : "r"(a0), "r"(a1), "r"(a2), "r"(a3), "r"(b0), "r"(b1));
}

// W[g][k] fp32 global -> fp16 smem, prescaled (0.5 i/f/o, 1.0 g gate);
// 16B chunk c of row g stored at chunk c ^ (g&7).
__device__ __forceinline__ void loadW(__half* Wt, const float* __restrict__ G) {
    for (int i = threadIdx.x; i < 8192; i += NT) {
        int g = i >> 5, w = i & 31;
        float sc = ((g >> 6) == 2) ? 1.0f : 0.5f;
        float2 v = *(const float2*)(G + g * 64 + 2 * w);
        int pos = (w >> 2) ^ (g & 7);
        *(__half2*)(Wt + g * 64 + pos * 8 + (w & 3) * 2) =
            __floats2half2_rn(v.x * sc, v.y * sc);
    }
}
__device__ __forceinline__ void loadSmall(float* wx, float* b0, float* b1,
                                          const float* Wih0,
                                          const float* Bi0, const float* Bh0,
                                          const float* Bi1, const float* Bh1) {
    for (int g = threadIdx.x; g < 256; g += NT) {
        float sc = ((g >> 6) == 2) ? 1.0f : 0.5f;
        wx[2 * g] = Wih0[2 * g] * sc;
        wx[2 * g + 1] = Wih0[2 * g + 1] * sc;
        b0[g] = (Bi0[g] + Bh0[g]) * sc;
        b1[g] = (Bi1[g] + Bh1[g]) * sc;
    }
}
// Load this warp's weight-fragment slice (units w*8..+8 of each gate).
__device__ __forceinline__ void loadFrags(uint32_t (*f)[8], uint32_t mbase,
                                          int w, uint32_t lmoff) {
#pragma unroll
    for (int gt = 0; gt < 4; gt++) {
        uint32_t a0 = mbase + (uint32_t)((gt * 64 + w * 8) * 128) + lmoff;
        ldm4(f[gt], a0);
        ldm4(f[gt] + 4, a0 ^ 64u);
    }
}
// Load one st-tile of A fragments (16 rows x 64 k).
__device__ __forceinline__ void ldA(uint32_t* f, uint32_t hA, int st,
                                    int arow, int acb, int j) {
#pragma unroll
    for (int kc = 0; kc < 4; kc++)
        ldm4(f + 4 * kc,
             hA + st * 2048 + arow * 128 + ((((kc << 1) | acb) ^ j) << 4));
}

// One layer step: warp covers units w*8..+8, all 128 rows.
// L0: gates = hA0 @ fWp^T (+ x@wx). fWp = persistent Whh0 frags.
// L1: gates = hA0 @ Wih1^T (reloaded from wWr) + hA1 @ fWp^T (fWp = Whh1, persistent),
//     with two independent accumulator sets (d, d2) for 8 parallel MMA chains.
template <bool L1MODE, bool HASX, bool FC>
__device__ __forceinline__ void stepLayer(
    uint32_t hA0, uint32_t hA1, __half* hout,
    const uint32_t (*fWp)[8], uint32_t wWr,
    const float* bias, const float* wx, const float* xb, int xstr,
    const float* fcw, float* fcpart, float* c,
    int w, int l4, int lm4, int arow, int acb, int j, uint32_t lmoff)
{
    uint32_t fWr[4][8];
    if (L1MODE) loadFrags(fWr, wWr, w, lmoff);
#pragma unroll
    for (int st = 0; st < 8; st++) {
        uint32_t faA[16];
        ldA(faA, hA0, st, arow, acb, j);
        float d[4][4];
#pragma unroll
        for (int gt = 0; gt < 4; gt++) {
            float2 bb = *(const float2*)(bias + gt * 64 + w * 8 + 2 * lm4);
            d[gt][0] = bb.x; d[gt][1] = bb.y; d[gt][2] = bb.x; d[gt][3] = bb.y;
        }
        if (L1MODE) {
            uint32_t faB[16];
            ldA(faB, hA1, st, arow, acb, j);
            float d2[4][4];
#pragma unroll
            for (int gt = 0; gt < 4; gt++)
                d2[gt][0] = d2[gt][1] = d2[gt][2] = d2[gt][3] = 0.f;
            // interleaved: 8 independent 4-deep chains
#pragma unroll
            for (int kc = 0; kc < 4; kc++)
#pragma unroll
                for (int gt = 0; gt < 4; gt++) {
                    mma16(d[gt], faA[4 * kc], faA[4 * kc + 1], faA[4 * kc + 2],
                          faA[4 * kc + 3], fWr[gt][2 * kc], fWr[gt][2 * kc + 1]);
                    mma16(d2[gt], faB[4 * kc], faB[4 * kc + 1], faB[4 * kc + 2],
                          faB[4 * kc + 3], fWp[gt][2 * kc], fWp[gt][2 * kc + 1]);
                }
#pragma unroll
            for (int gt = 0; gt < 4; gt++)
#pragma unroll
                for (int e = 0; e < 4; e++) d[gt][e] += d2[gt][e];
        } else {
#pragma unroll
            for (int kc = 0; kc < 4; kc++)
#pragma unroll
                for (int gt = 0; gt < 4; gt++)
                    mma16(d[gt], faA[4 * kc], faA[4 * kc + 1], faA[4 * kc + 2],
                          faA[4 * kc + 3], fWp[gt][2 * kc], fWp[gt][2 * kc + 1]);
        }
        float x0l, x1l, x0h, x1h;
        float4 wi, wf, wg, wo;
        if (HASX) {
            float2 va = *(const float2*)(xb + (st * 16 + l4) * xstr);
            float2 vb = *(const float2*)(xb + (st * 16 + l4 + 8) * xstr);
            x0l = va.x; x1l = va.y; x0h = vb.x; x1h = vb.y;
            wi = *(const float4*)(wx + w * 16 + 4 * lm4);
            wf = *(const float4*)(wx + 128 + w * 16 + 4 * lm4);
            wg = *(const float4*)(wx + 256 + w * 16 + 4 * lm4);
            wo = *(const float4*)(wx + 384 + w * 16 + 4 * lm4);
        }
        float hv[4];
#pragma unroll
        for (int e = 0; e < 4; e++) {
            const int o = e & 1;
            float gi = d[0][e], gf = d[1][e], gg = d[2][e], go = d[3][e];
            if (HASX) {
                float xa = (e < 2) ? x0l : x0h, xv = (e < 2) ? x1l : x1h;
                gi += xa * (o ? wi.z : wi.x) + xv * (o ? wi.w : wi.y);
                gf += xa * (o ? wf.z : wf.x) + xv * (o ? wf.w : wf.y);
                gg += xa * (o ? wg.z : wg.x) + xv * (o ? wg.w : wg.y);
                go += xa * (o ? wo.z : wo.x) + xv * (o ? wo.w : wo.y);
            }
            float ti = tanhg(gi), tf_ = tanhg(gf), tg = tanhg(gg), to = tanhg(go);
            float si = fmaf(0.5f, ti, 0.5f);
            float sf = fmaf(0.5f, tf_, 0.5f);
            float so = fmaf(0.5f, to, 0.5f);
            float cc = c[st * 4 + e];
            cc = fmaf(si, tg, sf * cc);
            c[st * 4 + e] = cc;
            hv[e] = so * tanhg(cc);
        }
        if (FC) {
            float2 f0v = *(const float2*)(fcw + w * 8 + 2 * lm4);
            float2 f1v = *(const float2*)(fcw + 64 + w * 8 + 2 * lm4);
            float sfc[4];
            sfc[0] = hv[0] * f0v.x + hv[1] * f0v.y;
            sfc[1] = hv[0] * f1v.x + hv[1] * f1v.y;
            sfc[2] = hv[2] * f0v.x + hv[3] * f0v.y;
            sfc[3] = hv[2] * f1v.x + hv[3] * f1v.y;
#pragma unroll
            for (int i = 0; i < 4; i++) {
                sfc[i] += __shfl_xor_sync(0xffffffffu, sfc[i], 1);
                sfc[i] += __shfl_xor_sync(0xffffffffu, sfc[i], 2);
            }
            if (lm4 == 0) {
                *(float2*)(fcpart + (st * 16 + l4) * 2) = make_float2(sfc[0], sfc[1]);
                *(float2*)(fcpart + (st * 16 + l4 + 8) * 2) = make_float2(sfc[2], sfc[3]);
            }
        }
        {
            __half2 plo = __floats2half2_rn(hv[0], hv[1]);
            __half2 phi = __floats2half2_rn(hv[2], hv[3]);
            int r0 = st * 16 + l4;
            int co = ((w ^ l4) << 4) + lm4 * 4;
            *(__half2*)((char*)hout + r0 * 128 + co) = plo;
            *(__half2*)((char*)hout + (r0 + 8) * 128 + co) = phi;
        }
    }
}

__global__ __launch_bounds__(NT, 1)
void SimpleLSTM_49709951484004_kernel(
    const float* __restrict__ obs,
    const float* __restrict__ eWih0, const float* __restrict__ eWhh0,
    const float* __restrict__ eBih0, const float* __restrict__ eBhh0,
    const float* __restrict__ eWih1, const float* __restrict__ eWhh1,
    const float* __restrict__ eBih1, const float* __restrict__ eBhh1,
    const float* __restrict__ dWih0, const float* __restrict__ dWhh0,
    const float* __restrict__ dBih0, const float* __restrict__ dBhh0,
    const float* __restrict__ dWih1, const float* __restrict__ dWhh1,
    const float* __restrict__ dBih1, const float* __restrict__ dBhh1,
    const float* __restrict__ fcW, const float* __restrict__ fcb,
    float* __restrict__ out, int Btot)
{
    extern __shared__ char smraw[];
    Smem* s = (Smem*)smraw;
    const int tid = threadIdx.x;
    const int w = tid >> 5, l = tid & 31, l4 = l >> 2, lm4 = l & 3;
    const int j = l & 7, tt = l >> 3;
    const uint32_t lmoff = (uint32_t)(j * 128 + (((tt ^ j) & 7) << 4)); // B-pattern
    const int arow = (l & 7) + ((l >> 3) & 1) * 8;                      // A-pattern
    const int acb = (l >> 4) & 1;
    const long base = (long)blockIdx.x * ROWS;

    for (int i = tid; i < ROWS * 16; i += NT)
        s->obs[i] = (base + i / 16 < Btot) ? obs[base * 16 + i] : 0.f;
    loadW(s->W[0], eWhh0); loadW(s->W[1], eWih1); loadW(s->W[2], eWhh1);
    loadSmall(s->wx, s->b0, s->b1, eWih0, eBih0, eBhh0, eBih1, eBhh1);
    if (tid < 128) s->fcw[tid] = fcW[tid];
    if (tid < 2) s->fcb[tid] = fcb[tid];
    for (int i = tid; i < 4096; i += NT) {
        ((uint32_t*)s->h0[0])[i] = 0u;
        ((uint32_t*)s->h1[0])[i] = 0u;
    }
    __syncthreads();

    const uint32_t uW = smem_u32(s->W[0]);
    const uint32_t uh0[2] = { smem_u32(s->h0[0]), smem_u32(s->h0[1]) };
    const uint32_t uh1[2] = { smem_u32(s->h1[0]), smem_u32(s->h1[1]) };

    // persistent weight fragments: Whh0 (L0) and Whh1 (L1, x h1_old)
    uint32_t fW0[4][8], fW1b[4][8];
    loadFrags(fW0, uW, w, lmoff);
    loadFrags(fW1b, uW + 65536u, w, lmoff);

    float c0[32], c1[32];
#pragma unroll
    for (int i = 0; i < 32; i++) { c0[i] = 0.f; c1[i] = 0.f; }
    int p0 = 0, p1 = 0;

    // ---------------- encoder: 8 steps (single barrier per pair) ----------------
#pragma unroll 1
    for (int t = 0; t < 8; t++) {
        stepLayer<false, true, false>(uh0[p0], 0u, s->h0[p0 ^ 1], fW0, 0u,
                                      s->b0, s->wx, s->obs + 2 * t, 16,
                                      nullptr, nullptr, c0,
                                      w, l4, lm4, arow, acb, j, lmoff);
        __syncthreads();
        stepLayer<true, false, false>(uh0[p0 ^ 1], uh1[p1], s->h1[p1 ^ 1],
                                      fW1b, uW + 32768u,
                                      s->b1, nullptr, nullptr, 0,
                                      nullptr, nullptr, c1,
                                      w, l4, lm4, arow, acb, j, lmoff);
        // no barrier needed here: next stage's post-L0 barrier fences h1
        p0 ^= 1; p1 ^= 1;
    }
    __syncthreads();

    // ---------------- phase switch ----------------
    loadW(s->W[0], dWhh0); loadW(s->W[1], dWih1); loadW(s->W[2], dWhh1);
    loadSmall(s->wx, s->b0, s->b1, dWih0, dBih0, dBhh0, dBih1, dBhh1);
    __syncthreads();
    loadFrags(fW0, uW, w, lmoff);
    loadFrags(fW1b, uW + 65536u, w, lmoff);

    // ---------------- decoder: 12 steps ----------------
#pragma unroll 1
    for (int t = 0; t < 12; t++) {
        const float* xb = (t == 0) ? (s->obs + 14) : s->pred;
        const int xstr = (t == 0) ? 16 : 2;
        stepLayer<false, true, false>(uh0[p0], 0u, s->h0[p0 ^ 1], fW0, 0u,
                                      s->b0, s->wx, xb, xstr,
                                      nullptr, nullptr, c0,
                                      w, l4, lm4, arow, acb, j, lmoff);
        __syncthreads();
        stepLayer<true, false, true>(uh0[p0 ^ 1], uh1[p1], s->h1[p1 ^ 1],
                                     fW1b, uW + 32768u,
                                     s->b1, nullptr, nullptr, 0,
                                     s->fcw, &s->fcpart[w][0][0], c1,
                                     w, l4, lm4, arow, acb, j, lmoff);
        __syncthreads();
        {
            int row = tid >> 1, o = tid & 1;
            float v = s->fcb[o];
#pragma unroll
            for (int w8 = 0; w8 < 8; w8++) v += s->fcpart[w8][row][o];
            s->pred[row * 2 + o] = v;
            long gr = base + row;
            if (gr < Btot) out[gr * 24 + t * 2 + o] = v;
        }
        __syncthreads();
        p0 ^= 1; p1 ^= 1;
    }
}

extern "C" void kernel_launch(void* const* d_in, const int* in_sizes, int n_in,
                              void* d_out, int out_size) {
    int Btot = in_sizes[0] / 16;
    int grid = (Btot + ROWS - 1) / ROWS;
    cudaFuncSetAttribute(SimpleLSTM_49709951484004_kernel,
                         cudaFuncAttributeMaxDynamicSharedMemorySize,
                         (int)sizeof(Smem));
    SimpleLSTM_49709951484004_kernel<<<grid, NT, sizeof(Smem)>>>(
        (const float*)d_in[0], (const float*)d_in[1], (const float*)d_in[2],
        (const float*)d_in[3], (const float*)d_in[4], (const float*)d_in[5],
        (const float*)d_in[6], (const float*)d_in[7], (const float*)d_in[8],
        (const float*)d_in[9], (const float*)d_in[10], (const float*)d_in[11],
        (const float*)d_in[12], (const float*)d_in[13], (const float*)d_in[14],
        (const float*)d_in[15], (const float*)d_in[16], (const float*)d_in[17],
        (const float*)d_in[18], (float*)d_out, Btot);
}

// round 17
// speedup vs baseline: 1.3846x; 1.1462x over previous
#include <cuda_runtime.h>
#include <cuda_fp16.h>
#include <cstdint>

#define NT 256
#define ROWS 128

struct Smem {
    __half W[3][16384];      // phase weights (swizzled, prescaled)
    __half h0[2][8192];      // [buf][row*64 + unit], 128B rows, 16B-chunk swizzle
    __half h1[2][8192];
    float4 c1s[8 * 256];     // layer-1 cell state [st][tid], lane-major
    float wx[512], b0[256], b1[256];
    float fcw[128], fcb[2];
    float fcpart[8][ROWS][2];
    float pred[ROWS * 2];
    float obs[ROWS * 16];
};

__device__ __forceinline__ float tanhg(float x) {
    float r; asm("tanh.approx.f32 %0, %1;" : "=f"(r) : "f"(x)); return r;
}
__device__ __forceinline__ uint32_t smem_u32(const void* p) {
    uint32_t a;
    asm("{ .reg .u64 t; cvta.to.shared.u64 t, %1; cvt.u32.u64 %0, t; }"
        : "=r"(a) : "l"(p));
    return a;
}
__device__ __forceinline__ void ldm4(uint32_t* f, uint32_t addr) {
    asm volatile("ldmatrix.sync.aligned.m8n8.x4.shared.b16 {%0,%1,%2,%3}, [%4];"
        : "=r"(f[0]), "=r"(f[1]), "=r"(f[2]), "=r"(f[3]) : "r"(addr));
}
__device__ __forceinline__ void mma16(float* d, uint32_t a0, uint32_t a1,
                                      uint32_t a2, uint32_t a3,
                                      uint32_t b0, uint32_t b1) {
    asm volatile(
        "mma.sync.aligned.m16n8k16.row.col.f32.f16.f16.f32 "
        "{%0,%1,%2,%3},{%4,%5,%6,%7},{%8,%9},{%0,%1,%2,%3};"
        : "+f"(d[0]), "+f"(d[1]), "+f"(d[2]), "+f"(d[3])
        : "r"(a0), "r"(a1), "r"(a2), "r"(a3), "r"(b0), "r"(b1));
}

// W[g][k] fp32 global -> fp16 smem, prescaled (0.5 i/f/o, 1.0 g gate);
// 16B chunk c of row g stored at chunk c ^ (g&7).
__device__ __forceinline__ void loadW(__half* Wt, const float* __restrict__ G) {
    for (int i = threadIdx.x; i < 8192; i += NT) {
        int g = i >> 5, w = i & 31;
        float sc = ((g >> 6) == 2) ? 1.0f : 0.5f;
        float2 v = *(const float2*)(G + g * 64 + 2 * w);
        int pos = (w >> 2) ^ (g & 7);
        *(__half2*)(Wt + g * 64 + pos * 8 + (w & 3) * 2) =
            __floats2half2_rn(v.x * sc, v.y * sc);
    }
}
__device__ __forceinline__ void loadSmall(float* wx, float* b0, float* b1,
                                          const float* Wih0,
                                          const float* Bi0, const float* Bh0,
                                          const float* Bi1, const float* Bh1) {
    for (int g = threadIdx.x; g < 256; g += NT) {
        float sc = ((g >> 6) == 2) ? 1.0f : 0.5f;
        wx[2 * g] = Wih0[2 * g] * sc;
        wx[2 * g + 1] = Wih0[2 * g + 1] * sc;
        b0[g] = (Bi0[g] + Bh0[g]) * sc;
        b1[g] = (Bi1[g] + Bh1[g]) * sc;
    }
}
// Load this warp's weight-fragment slice (units w*8..+8 of each gate).
__device__ __forceinline__ void loadFrags(uint32_t (*f)[8], uint32_t mbase,
                                          int w, uint32_t lmoff) {
#pragma unroll
    for (int gt = 0; gt < 4; gt++) {
        uint32_t a0 = mbase + (uint32_t)((gt * 64 + w * 8) * 128) + lmoff;
        ldm4(f[gt], a0);
        ldm4(f[gt] + 4, a0 ^ 64u);
    }
}
// Load one st-tile of A fragments (16 rows x 64 k).
__device__ __forceinline__ void ldA(uint32_t* f, uint32_t hA, int st,
                                    int arow, int acb, int j) {
#pragma unroll
    for (int kc = 0; kc < 4; kc++)
        ldm4(f + 4 * kc,
             hA + st * 2048 + arow * 128 + ((((kc << 1) | acb) ^ j) << 4));
}
__device__ __forceinline__ void biasInit(float* d, const float* bias, int bofs) {
#pragma unroll
    for (int gt = 0; gt < 4; gt++) {
        float2 bb = *(const float2*)(bias + gt * 64 + bofs);
        d[gt * 4 + 0] = bb.x; d[gt * 4 + 1] = bb.y;
        d[gt * 4 + 2] = bb.x; d[gt * 4 + 3] = bb.y;
    }
}
__device__ __forceinline__ void gemmChain(float* d, const uint32_t* fa,
                                          const uint32_t (*fW)[8]) {
#pragma unroll
    for (int kc = 0; kc < 4; kc++)
#pragma unroll
        for (int gt = 0; gt < 4; gt++)
            mma16(d + gt * 4, fa[4 * kc], fa[4 * kc + 1], fa[4 * kc + 2],
                  fa[4 * kc + 3], fW[gt][2 * kc], fW[gt][2 * kc + 1]);
}

// Software-pipelined layer step: GEMM(st+1) issued before epilogue(st) so
// tensor-pipe work overlaps the MUFU/FMA cell math. Warp covers units
// w*8..+8, all 128 rows. L1MODE: gates = hA0@fWa^T + hA1@fWb^T; cell state
// in smem (cSm). Else: gates = hA0@fWa^T (+x@wx); cell state in regs (cReg).
template <bool L1MODE, bool HASX, bool FC>
__device__ __forceinline__ void stepLayer(
    uint32_t hA0, uint32_t hA1, __half* hout,
    const uint32_t (*fWa)[8], const uint32_t (*fWb)[8],
    const float* bias, const float* wx, const float* xb, int xstr,
    const float* fcw, float* fcpart, float* cReg, float4* cSm,
    int w, int l4, int lm4, int arow, int acb, int j, int tid)
{
    const int bofs = w * 8 + 2 * lm4;
    float dbuf[2][16];
    uint32_t fa[16], fb[16];

    ldA(fa, hA0, 0, arow, acb, j);
    if (L1MODE) ldA(fb, hA1, 0, arow, acb, j);
    biasInit(dbuf[0], bias, bofs);
    gemmChain(dbuf[0], fa, fWa);
    if (L1MODE) gemmChain(dbuf[0], fb, fWb);

#pragma unroll
    for (int st = 0; st < 8; st++) {
        float* dC = dbuf[st & 1];
        float* dN = dbuf[(st & 1) ^ 1];
        if (st < 7) {   // issue next tile's GEMM before this tile's epilogue
            ldA(fa, hA0, st + 1, arow, acb, j);
            if (L1MODE) ldA(fb, hA1, st + 1, arow, acb, j);
            biasInit(dN, bias, bofs);
            gemmChain(dN, fa, fWa);
            if (L1MODE) gemmChain(dN, fb, fWb);
        }
        float x0l, x1l, x0h, x1h;
        float4 wi, wf, wg, wo;
        if (HASX) {
            float2 va = *(const float2*)(xb + (st * 16 + l4) * xstr);
            float2 vb = *(const float2*)(xb + (st * 16 + l4 + 8) * xstr);
            x0l = va.x; x1l = va.y; x0h = vb.x; x1h = vb.y;
            wi = *(const float4*)(wx + w * 16 + 4 * lm4);
            wf = *(const float4*)(wx + 128 + w * 16 + 4 * lm4);
            wg = *(const float4*)(wx + 256 + w * 16 + 4 * lm4);
            wo = *(const float4*)(wx + 384 + w * 16 + 4 * lm4);
        }
        float4 cv;
        if (L1MODE) cv = cSm[st * 256 + tid];
        float hv[4];
#pragma unroll
        for (int e = 0; e < 4; e++) {
            const int o = e & 1;
            float gi = dC[e], gf = dC[4 + e], gg = dC[8 + e], go = dC[12 + e];
            if (HASX) {
                float xa = (e < 2) ? x0l : x0h, xv = (e < 2) ? x1l : x1h;
                gi += xa * (o ? wi.z : wi.x) + xv * (o ? wi.w : wi.y);
                gf += xa * (o ? wf.z : wf.x) + xv * (o ? wf.w : wf.y);
                gg += xa * (o ? wg.z : wg.x) + xv * (o ? wg.w : wg.y);
                go += xa * (o ? wo.z : wo.x) + xv * (o ? wo.w : wo.y);
            }
            float ti = tanhg(gi), tf_ = tanhg(gf), tg = tanhg(gg), to = tanhg(go);
            float si = fmaf(0.5f, ti, 0.5f);
            float sf = fmaf(0.5f, tf_, 0.5f);
            float so = fmaf(0.5f, to, 0.5f);
            float cc = L1MODE ? (&cv.x)[e] : cReg[st * 4 + e];
            cc = fmaf(si, tg, sf * cc);
            if (L1MODE) (&cv.x)[e] = cc; else cReg[st * 4 + e] = cc;
            hv[e] = so * tanhg(cc);
        }
        if (L1MODE) cSm[st * 256 + tid] = cv;
        if (FC) {
            float2 f0v = *(const float2*)(fcw + w * 8 + 2 * lm4);
            float2 f1v = *(const float2*)(fcw + 64 + w * 8 + 2 * lm4);
            float sfc[4];
            sfc[0] = hv[0] * f0v.x + hv[1] * f0v.y;
            sfc[1] = hv[0] * f1v.x + hv[1] * f1v.y;
            sfc[2] = hv[2] * f0v.x + hv[3] * f0v.y;
            sfc[3] = hv[2] * f1v.x + hv[3] * f1v.y;
#pragma unroll
            for (int i = 0; i < 4; i++) {
                sfc[i] += __shfl_xor_sync(0xffffffffu, sfc[i], 1);
                sfc[i] += __shfl_xor_sync(0xffffffffu, sfc[i], 2);
            }
            if (lm4 == 0) {
                *(float2*)(fcpart + (st * 16 + l4) * 2) = make_float2(sfc[0], sfc[1]);
                *(float2*)(fcpart + (st * 16 + l4 + 8) * 2) = make_float2(sfc[2], sfc[3]);
            }
        }
        {
            __half2 plo = __floats2half2_rn(hv[0], hv[1]);
            __half2 phi = __floats2half2_rn(hv[2], hv[3]);
            int r0 = st * 16 + l4;
            int co = ((w ^ l4) << 4) + lm4 * 4;
            *(__half2*)((char*)hout + r0 * 128 + co) = plo;
            *(__half2*)((char*)hout + (r0 + 8) * 128 + co) = phi;
        }
    }
}

__global__ __launch_bounds__(NT, 1)
void SimpleLSTM_49709951484004_kernel(
    const float* __restrict__ obs,
    const float* __restrict__ eWih0, const float* __restrict__ eWhh0,
    const float* __restrict__ eBih0, const float* __restrict__ eBhh0,
    const float* __restrict__ eWih1, const float* __restrict__ eWhh1,
    const float* __restrict__ eBih1, const float* __restrict__ eBhh1,
    const float* __restrict__ dWih0, const float* __restrict__ dWhh0,
    const float* __restrict__ dBih0, const float* __restrict__ dBhh0,
    const float* __restrict__ dWih1, const float* __restrict__ dWhh1,
    const float* __restrict__ dBih1, const float* __restrict__ dBhh1,
    const float* __restrict__ fcW, const float* __restrict__ fcb,
    float* __restrict__ out, int Btot)
{
    extern __shared__ char smraw[];
    Smem* s = (Smem*)smraw;
    const int tid = threadIdx.x;
    const int w = tid >> 5, l = tid & 31, l4 = l >> 2, lm4 = l & 3;
    const int j = l & 7, tt = l >> 3;
    const uint32_t lmoff = (uint32_t)(j * 128 + (((tt ^ j) & 7) << 4)); // B-pattern
    const int arow = (l & 7) + ((l >> 3) & 1) * 8;                      // A-pattern
    const int acb = (l >> 4) & 1;
    const long base = (long)blockIdx.x * ROWS;

    for (int i = tid; i < ROWS * 16; i += NT)
        s->obs[i] = (base + i / 16 < Btot) ? obs[base * 16 + i] : 0.f;
    loadW(s->W[0], eWhh0); loadW(s->W[1], eWih1); loadW(s->W[2], eWhh1);
    loadSmall(s->wx, s->b0, s->b1, eWih0, eBih0, eBhh0, eBih1, eBhh1);
    if (tid < 128) s->fcw[tid] = fcW[tid];
    if (tid < 2) s->fcb[tid] = fcb[tid];
    for (int i = tid; i < 4096; i += NT) {
        ((uint32_t*)s->h0[0])[i] = 0u;
        ((uint32_t*)s->h1[0])[i] = 0u;
    }
    for (int i = tid; i < 8192; i += NT)
        ((uint32_t*)s->c1s)[i] = 0u;
    __syncthreads();

    const uint32_t uW = smem_u32(s->W[0]);
    const uint32_t uh0[2] = { smem_u32(s->h0[0]), smem_u32(s->h0[1]) };
    const uint32_t uh1[2] = { smem_u32(s->h1[0]), smem_u32(s->h1[1]) };

    // all-persistent weight fragments (champion config)
    uint32_t fW0[4][8], fW1a[4][8], fW1b[4][8];
    loadFrags(fW0, uW, w, lmoff);
    loadFrags(fW1a, uW + 32768u, w, lmoff);
    loadFrags(fW1b, uW + 65536u, w, lmoff);

    float c0[32];
#pragma unroll
    for (int i = 0; i < 32; i++) c0[i] = 0.f;
    int p0 = 0, p1 = 0;

    // ---------------- encoder: 8 steps (single barrier per pair) ----------------
#pragma unroll 1
    for (int t = 0; t < 8; t++) {
        stepLayer<false, true, false>(uh0[p0], 0u, s->h0[p0 ^ 1], fW0, fW0,
                                      s->b0, s->wx, s->obs + 2 * t, 16,
                                      nullptr, nullptr, c0, nullptr,
                                      w, l4, lm4, arow, acb, j, tid);
        __syncthreads();
        stepLayer<true, false, false>(uh0[p0 ^ 1], uh1[p1], s->h1[p1 ^ 1],
                                      fW1a, fW1b,
                                      s->b1, nullptr, nullptr, 0,
                                      nullptr, nullptr, nullptr, s->c1s,
                                      w, l4, lm4, arow, acb, j, tid);
        // next pair's post-L0 barrier fences all h1 accesses
        p0 ^= 1; p1 ^= 1;
    }
    __syncthreads();

    // ---------------- phase switch ----------------
    loadW(s->W[0], dWhh0); loadW(s->W[1], dWih1); loadW(s->W[2], dWhh1);
    loadSmall(s->wx, s->b0, s->b1, dWih0, dBih0, dBhh0, dBih1, dBhh1);
    __syncthreads();
    loadFrags(fW0, uW, w, lmoff);
    loadFrags(fW1a, uW + 32768u, w, lmoff);
    loadFrags(fW1b, uW + 65536u, w, lmoff);

    // ---------------- decoder: 12 steps ----------------
#pragma unroll 1
    for (int t = 0; t < 12; t++) {
        const float* xb = (t == 0) ? (s->obs + 14) : s->pred;
        const int xstr = (t == 0) ? 16 : 2;
        stepLayer<false, true, false>(uh0[p0], 0u, s->h0[p0 ^ 1], fW0, fW0,
                                      s->b0, s->wx, xb, xstr,
                                      nullptr, nullptr, c0, nullptr,
                                      w, l4, lm4, arow, acb, j, tid);
        __syncthreads();
        stepLayer<true, false, true>(uh0[p0 ^ 1], uh1[p1], s->h1[p1 ^ 1],
                                     fW1a, fW1b,
                                     s->b1, nullptr, nullptr, 0,
                                     s->fcw, &s->fcpart[w][0][0], nullptr, s->c1s,
                                     w, l4, lm4, arow, acb, j, tid);
        __syncthreads();
        {
            int row = tid >> 1, o = tid & 1;
            float v = s->fcb[o];
#pragma unroll
            for (int w8 = 0; w8 < 8; w8++) v += s->fcpart[w8][row][o];
            s->pred[row * 2 + o] = v;
            long gr = base + row;
            if (gr < Btot) out[gr * 24 + t * 2 + o] = v;
        }
        __syncthreads();
        p0 ^= 1; p1 ^= 1;
    }
}

extern "C" void kernel_launch(void* const* d_in, const int* in_sizes, int n_in,
                              void* d_out, int out_size) {
    int Btot = in_sizes[0] / 16;
    int grid = (Btot + ROWS - 1) / ROWS;
    cudaFuncSetAttribute(SimpleLSTM_49709951484004_kernel,
                         cudaFuncAttributeMaxDynamicSharedMemorySize,
                         (int)sizeof(Smem));
    SimpleLSTM_49709951484004_kernel<<<grid, NT, sizeof(Smem)>>>(
        (const float*)d_in[0], (const float*)d_in[1], (const float*)d_in[2],
        (const float*)d_in[3], (const float*)d_in[4], (const float*)d_in[5],
        (const float*)d_in[6], (const float*)d_in[7], (const float*)d_in[8],
        (const float*)d_in[9], (const float*)d_in[10], (const float*)d_in[11],
        (const float*)d_in[12], (const float*)d_in[13], (const float*)d_in[14],
        (const float*)d_in[15], (const float*)d_in[16], (const float*)d_in[17],
        (const float*)d_in[18], (float*)d_out, Btot);
}